// round 12
// baseline (speedup 1.0000x reference)
#include <cuda_runtime.h>
#include <cstdint>

#define D        768
#define DV       (D / 4)     // 192 float4 per row
#define E        8
#define RB       4           // rows per warp-batch
#define NJ       6           // k-iterations (32 float4 per iter)
#define WRP      8           // warps per CTA
#define THREADS  256
#define SLOT     (RB * DV)           // 768 float4 = 12 KB per buffer
#define SLOT_BYTES (RB * D * 4)      // 12288

typedef unsigned long long ull;

// packed 2-wide fp32 FMA: d = a*b + d
__device__ __forceinline__ void ffma2(ull& d, ull a, ull b) {
    asm("fma.rn.f32x2 %0, %1, %2, %0;" : "+l"(d) : "l"(a), "l"(b));
}
__device__ __forceinline__ uint32_t s2u(const void* p) {
    uint32_t a;
    asm("{ .reg .u64 t; cvta.to.shared.u64 t, %1; cvt.u32.u64 %0, t; }"
        : "=r"(a) : "l"(p));
    return a;
}
__device__ __forceinline__ void mbar_init(uint32_t m, uint32_t cnt) {
    asm volatile("mbarrier.init.shared.b64 [%0], %1;" :: "r"(m), "r"(cnt) : "memory");
}
__device__ __forceinline__ void mbar_expect_tx(uint32_t m, uint32_t bytes) {
    asm volatile("mbarrier.arrive.expect_tx.shared.b64 _, [%0], %1;"
                 :: "r"(m), "r"(bytes) : "memory");
}
__device__ __forceinline__ void mbar_wait(uint32_t m, uint32_t phase) {
    asm volatile(
        "{\n\t"
        ".reg .pred P1;\n\t"
        "LAB_WAIT_%=:\n\t"
        "mbarrier.try_wait.parity.acquire.cta.shared::cta.b64 P1, [%0], %1, 0x989680;\n\t"
        "@P1 bra LAB_DONE_%=;\n\t"
        "bra LAB_WAIT_%=;\n\t"
        "LAB_DONE_%=:\n\t"
        "}"
        :: "r"(m), "r"(phase) : "memory");
}
// 1D bulk copy global -> shared (TMA engine, no per-warp LSU traffic)
__device__ __forceinline__ void bulk_g2s(uint32_t dst, const void* src,
                                         uint32_t bytes, uint32_t m) {
    asm volatile(
        "cp.async.bulk.shared::cta.global.mbarrier::complete_tx::bytes [%0], [%1], %2, [%3];"
        :: "r"(dst), "l"(src), "r"(bytes), "r"(m) : "memory");
}
// fire-and-forget DRAM -> L2 prefetch: no mbarrier, no smem, no SM tracking.
// Turns the later demand bulk_g2s into an L2 hit (~250 cyc vs ~577 cyc).
__device__ __forceinline__ void bulk_prefetch_l2(const void* src, uint32_t bytes) {
    asm volatile("cp.async.bulk.prefetch.L2.global [%0], %1;"
                 :: "l"(src), "r"(bytes) : "memory");
}

__global__ __launch_bounds__(THREADS, 1)
void router_kernel(const float* __restrict__ h,
                   const float* __restrict__ gw,
                   const float* __restrict__ gb,
                   float* __restrict__ out, int B) {
    extern __shared__ float4 smem[];
    float4* ws   = smem;                        // 1536 float4 = 24 KB (row-major w)
    float4* xbuf = smem + 8 * DV;               // WRP*2*SLOT = 192 KB staging
    float*  b_sh = (float*)(xbuf + WRP * 2 * SLOT);   // 8 floats
    uint64_t* mbars = (uint64_t*)(b_sh + 8);    // 16 mbarriers (warp, buf)

    const float4* gw4 = reinterpret_cast<const float4*>(gw);
    for (int i = threadIdx.x; i < 8 * DV; i += THREADS)
        ws[i] = gw4[i];
    if (threadIdx.x < E) b_sh[threadIdx.x] = gb[threadIdx.x];

    if (threadIdx.x == 0) {
        for (int i = 0; i < WRP * 2; i++)
            mbar_init(s2u(mbars) + 8u * i, 1);
        asm volatile("fence.proxy.async.shared::cta;" ::: "memory");
    }
    __syncthreads();   // the ONLY CTA-wide sync in the kernel

    const ulonglong2* wsu = reinterpret_cast<const ulonglong2*>(ws);

    const int lane   = threadIdx.x & 31;
    const int warp   = threadIdx.x >> 5;
    const int gwarp  = blockIdx.x * WRP + warp;
    const int nwarps = gridDim.x * WRP;
    const int nbatch = B / RB;                  // 8192

    // warp-private double buffer + mbarriers
    float4* xw = xbuf + warp * (2 * SLOT);
    const uint32_t xs0 = s2u(xw);
    const uint32_t xs1 = xs0 + SLOT_BYTES;
    const uint32_t mb0 = s2u(mbars) + (uint32_t)warp * 16u;
    const uint32_t mb1 = mb0 + 8u;

    float* out_idx = out;                       // [B,2] indices (as float)
    float* out_wt  = out + (size_t)2 * B;       // [B,2] weights
    float* out_lg  = out + (size_t)4 * B;       // [B,8] logits

    // prologue: issue first two demand fetches + L2 prefetch for the next ones
    if (lane == 0) {
        if (gwarp < nbatch) {
            mbar_expect_tx(mb0, SLOT_BYTES);
            bulk_g2s(xs0, h + (size_t)gwarp * RB * D, SLOT_BYTES, mb0);
        }
        if (gwarp + nwarps < nbatch) {
            mbar_expect_tx(mb1, SLOT_BYTES);
            bulk_g2s(xs1, h + (size_t)(gwarp + nwarps) * RB * D, SLOT_BYTES, mb1);
        }
        #pragma unroll
        for (int k = 2; k < 4; k++) {
            const int pb = gwarp + k * nwarps;
            if (pb < nbatch)
                bulk_prefetch_l2(h + (size_t)pb * RB * D, SLOT_BYTES);
        }
    }

    int i = 0;
    for (int batch = gwarp; batch < nbatch; batch += nwarps, i++) {
        const int buf = i & 1;
        mbar_wait(buf ? mb1 : mb0, (i >> 1) & 1);   // wait own 12 KB only

        const float4* xt = xw + buf * SLOT;
        const int row0 = batch * RB;

        // acc2[r][e]: packed k-pairs (low = even pair, high = odd pair)
        ull acc2[RB][E];
        #pragma unroll
        for (int r = 0; r < RB; r++)
            #pragma unroll
            for (int e = 0; e < E; e++) acc2[r][e] = 0ull;

        #pragma unroll
        for (int j = 0; j < NJ; j++) {
            const int k4 = j * 32 + lane;
            ulonglong2 xu[RB];
            #pragma unroll
            for (int r = 0; r < RB; r++)
                xu[r] = *reinterpret_cast<const ulonglong2*>(&xt[r * DV + k4]);
            #pragma unroll
            for (int e = 0; e < E; e++) {
                const ulonglong2 we = wsu[e * DV + k4];
                #pragma unroll
                for (int r = 0; r < RB; r++) {
                    ffma2(acc2[r][e], we.x, xu[r].x);
                    ffma2(acc2[r][e], we.y, xu[r].y);
                }
            }
        }

        // refill this slot with batch i+2 (demand, should hit L2 now),
        // and prefetch batch i+4 DRAM -> L2 (fire-and-forget).
        __syncwarp();
        if (lane == 0) {
            const int nb = batch + 2 * nwarps;
            if (nb < nbatch) {
                const uint32_t mbn = buf ? mb1 : mb0;
                mbar_expect_tx(mbn, SLOT_BYTES);
                bulk_g2s(buf ? xs1 : xs0, h + (size_t)nb * RB * D, SLOT_BYTES, mbn);
            }
            const int pb = batch + 4 * nwarps;
            if (pb < nbatch)
                bulk_prefetch_l2(h + (size_t)pb * RB * D, SLOT_BYTES);
        }

        // unpack + horizontal add: v[r*8 + e]
        float v[RB * E];
        #pragma unroll
        for (int r = 0; r < RB; r++)
            #pragma unroll
            for (int e = 0; e < E; e++) {
                uint32_t lo, hi;
                asm("mov.b64 {%0, %1}, %2;" : "=r"(lo), "=r"(hi) : "l"(acc2[r][e]));
                v[r * E + e] = __uint_as_float(lo) + __uint_as_float(hi);
            }

        // Butterfly transpose-reduction: lane l ends with the full k-sum of
        // value index l (row l>>3, expert l&7).
        #pragma unroll
        for (int off = 16; off >= 1; off >>= 1) {
            const bool up = (lane & off) != 0;
            #pragma unroll
            for (int q = 0; q < off; q++) {
                float send = up ? v[q] : v[q + off];
                float recv = __shfl_xor_sync(0xffffffffu, send, off);
                v[q] = (up ? v[q + off] : v[q]) + recv;
            }
        }

        const int e   = lane & 7;
        const int row = row0 + (lane >> 3);
        const float logit = v[0] + b_sh[e];

        out_lg[(size_t)row * E + e] = logit;     // 32 consecutive floats/warp

        float lv[8];
        #pragma unroll
        for (int k = 0; k < 8; k++)
            lv[k] = __shfl_sync(0xffffffffu, logit, (lane & 24) | k);

        if (e == 0) {
            // top-1: strict >, lowest index wins ties (matches lax.top_k)
            int i1 = 0; float v1 = lv[0];
            #pragma unroll
            for (int k = 1; k < 8; k++)
                if (lv[k] > v1) { v1 = lv[k]; i1 = k; }
            int i2 = (i1 == 0) ? 1 : 0; float v2 = lv[i2];
            #pragma unroll
            for (int k = 0; k < 8; k++)
                if (k != i1 && lv[k] > v2) { v2 = lv[k]; i2 = k; }

            const float tt = __expf(v2 - v1);     // <= 1
            const float w1 = 1.0f / (1.0f + tt);
            const float w2 = tt * w1;

            out_idx[(size_t)row * 2]     = (float)i1;
            out_idx[(size_t)row * 2 + 1] = (float)i2;
            out_wt [(size_t)row * 2]     = w1;
            out_wt [(size_t)row * 2 + 1] = w2;
        }
    }
}

extern "C" void kernel_launch(void* const* d_in, const int* in_sizes, int n_in,
                              void* d_out, int out_size) {
    const float* h  = (const float*)d_in[0];   // [B, 768]
    const float* gw = (const float*)d_in[1];   // [8, 768]
    const float* gb = (const float*)d_in[2];   // [8]
    float* out = (float*)d_out;

    const int B = in_sizes[0] / D;             // 32768

    // smem: 24KB w + 192KB warp-private staging + bias + 16 mbarriers
    const int smem_bytes = (8 * DV + WRP * 2 * SLOT) * 16 + 64 + 16 * 8;
    cudaFuncSetAttribute(router_kernel,
                         cudaFuncAttributeMaxDynamicSharedMemorySize, smem_bytes);

    // persistent: 1 CTA per SM, warps self-paced over 8192 batches
    const int blocks = 148;
    router_kernel<<<blocks, THREADS, smem_bytes>>>(h, gw, gb, out, B);
}